// round 7
// baseline (speedup 1.0000x reference)
#include <cuda_runtime.h>
#include <cuda_bf16.h>

typedef unsigned long long ull;

// Problem-fixed capacities (N=50000, E=800000, d_hid=128, d_out=64, 64 graphs)
#define MAXN 50000
#define MAXE 800000

// ---------------- scratch (device globals; no runtime allocation) ----------
__device__ float g_xws1[MAXN * 128];   // x @ W1 (UNSCALED)
__device__ float g_h[MAXN * 128];      // relu layer-1 output
__device__ float g_xws2[MAXN * 64];    // dinv * (h @ W2)
__device__ float g_dinv[MAXN];
__device__ int   g_cnt[MAXN];
__device__ int   g_cursor[MAXN];
__device__ int   g_rowptr[MAXN + 1];
__device__ int   g_colidx[MAXE];
__device__ int   g_src[MAXE];
__device__ int   g_dst[MAXE];
__device__ int   g_batch[MAXN];
__device__ float g_gsum[64 * 64];
__device__ float g_gcnt[64];
__device__ int   g_flag64;

// ---------------- f32x2 helpers (packed fp32 FMA, sm_100+) -----------------
__device__ __forceinline__ ull pack2(float a, float b) {
    ull r;
    asm("mov.b64 %0, {%1, %2};" : "=l"(r) : "f"(a), "f"(b));
    return r;
}
__device__ __forceinline__ float2 unpack2(ull v) {
    float2 r;
    asm("mov.b64 {%0, %1}, %2;" : "=f"(r.x), "=f"(r.y) : "l"(v));
    return r;
}
__device__ __forceinline__ void fma2(ull& d, ull a, ull b) {
    asm("fma.rn.f32x2 %0, %1, %2, %0;" : "+l"(d) : "l"(a), "l"(b));
}

// ---------------- setup: init scratch + dtype detect (fused) ---------------
__global__ void k_init_detect(int N, const void* edges) {
    int i = blockIdx.x * blockDim.x + threadIdx.x;
    if (i < N) { g_cnt[i] = 0; g_cursor[i] = 0; }
    if (i < 64 * 64) g_gsum[i] = 0.0f;
    if (i < 64) g_gcnt[i] = 0.0f;
    if (i == 0) {
        const long long* p = (const long long*)edges;
        long long v[8];
        #pragma unroll
        for (int k = 0; k < 8; k++) v[k] = p[k];
        int ok = 1;
        #pragma unroll
        for (int k = 0; k < 8; k++)
            if (v[k] < 0 || v[k] > 0x7fffffffLL) ok = 0;
        g_flag64 = ok;
    }
}

// Fused: edge conversion + degree count + batch conversion + graph-size hist.
__global__ void k_conv_fused(const void* edges, const void* bp,
                             int E, int N, int NG) {
    __shared__ int sh[64];
    int tid = threadIdx.x;
    if (tid < 64) sh[tid] = 0;
    __syncthreads();
    int e = blockIdx.x * blockDim.x + tid;
    int f64 = g_flag64;
    if (e < E) {
        long long s, d;
        if (f64) {
            const long long* p = (const long long*)edges;
            s = p[e]; d = p[(size_t)E + e];
        } else {
            const int* p = (const int*)edges;
            s = p[e]; d = p[E + e];
        }
        if (s < 0) s = 0; if (s >= N) s = N - 1;
        if (d < 0) d = 0; if (d >= N) d = N - 1;
        g_src[e] = (int)s;
        g_dst[e] = (int)d;
        atomicAdd(&g_cnt[(int)d], 1);
    }
    if (e < N) {
        long long b;
        if (f64) b = ((const long long*)bp)[e];
        else     b = ((const int*)bp)[e];
        if (b < 0) b = 0; if (b >= NG) b = NG - 1;
        g_batch[e] = (int)b;
        atomicAdd(&sh[(int)b], 1);
    }
    __syncthreads();
    if (tid < 64 && sh[tid] != 0)
        atomicAdd(&g_gcnt[tid], (float)sh[tid]);
}

// Single-block thread-coarsened exclusive scan: g_cnt -> g_rowptr, + dinv.
__global__ __launch_bounds__(1024)
void k_scan1(int n) {
    const int T = 1024;
    __shared__ int ws[32];
    int tid = threadIdx.x, lane = tid & 31, wid = tid >> 5;
    int per = (n + T - 1) / T;
    int start = tid * per;
    int end = start + per; if (end > n) end = n;
    int sum = 0;
    for (int i = start; i < end; i++) sum += g_cnt[i];
    int incl = sum;
    #pragma unroll
    for (int o = 1; o < 32; o <<= 1) {
        int t = __shfl_up_sync(0xffffffffu, incl, o);
        if (lane >= o) incl += t;
    }
    if (lane == 31) ws[wid] = incl;
    __syncthreads();
    if (wid == 0) {
        int w = ws[lane];
        int wincl = w;
        #pragma unroll
        for (int o = 1; o < 32; o <<= 1) {
            int t = __shfl_up_sync(0xffffffffu, wincl, o);
            if (lane >= o) wincl += t;
        }
        ws[lane] = wincl - w;
    }
    __syncthreads();
    int run = (incl - sum) + ws[wid];
    for (int i = start; i < end; i++) {
        int v = g_cnt[i];
        g_rowptr[i] = run;
        g_dinv[i] = rsqrtf((float)v + 1.0f);   // +1 self loop
        run += v;
    }
    if (tid == T - 1) g_rowptr[n] = run;
}

__global__ void k_fill(int E) {
    int e = blockIdx.x * blockDim.x + threadIdx.x;
    if (e >= E) return;
    int d = g_dst[e];
    int pos = atomicAdd(&g_cursor[d], 1);
    g_colidx[g_rowptr[d] + pos] = g_src[e];
}

// ---------------- GEMM: out[m][:] = (dinv[m]?) * (X[m][:] @ W) -------------
template <int BN, int NT, bool SCALE>
__global__ __launch_bounds__(NT, 1)
void gemm_kernel(const float* __restrict__ X, const float* __restrict__ W,
                 float* __restrict__ out, int M, int K) {
    constexpr int BM = 128, BK = 32;
    __shared__ float xs[BK][BM + 4];
    __shared__ float ws[BK][BN];

    int tid = threadIdx.x;
    int cx = tid % (BN / 8);
    int cy = tid / (BN / 8);
    int m0 = blockIdx.x * BM;

    ull acc[8][4];
    #pragma unroll
    for (int i = 0; i < 8; i++)
        #pragma unroll
        for (int j = 0; j < 4; j++) acc[i][j] = 0ull;

    for (int kt = 0; kt < K; kt += BK) {
        #pragma unroll
        for (int l = 0; l < (BM * BK / 4) / NT; l++) {
            int idx = tid + l * NT;
            int r = idx >> 3;
            int kq = idx & 7;
            int grow = m0 + r;
            if (grow >= M) grow = M - 1;
            float4 v = __ldg((const float4*)(X + (size_t)grow * K + kt + kq * 4));
            xs[kq * 4 + 0][r] = v.x;
            xs[kq * 4 + 1][r] = v.y;
            xs[kq * 4 + 2][r] = v.z;
            xs[kq * 4 + 3][r] = v.w;
        }
        #pragma unroll
        for (int l = 0; l < (BK * BN / 4) / NT; l++) {
            int idx = tid + l * NT;
            int wr = idx / (BN / 4);
            int wc = idx % (BN / 4);
            float4 v = __ldg((const float4*)(W + (size_t)(kt + wr) * BN + wc * 4));
            *(float4*)&ws[wr][wc * 4] = v;
        }
        __syncthreads();

        #pragma unroll
        for (int kk = 0; kk < BK; kk++) {
            float4 a0 = *(const float4*)&xs[kk][cy * 8];
            float4 a1 = *(const float4*)&xs[kk][cy * 8 + 4];
            float4 b0 = *(const float4*)&ws[kk][cx * 8];
            float4 b1 = *(const float4*)&ws[kk][cx * 8 + 4];
            ull bb0 = pack2(b0.x, b0.y), bb1 = pack2(b0.z, b0.w);
            ull bb2 = pack2(b1.x, b1.y), bb3 = pack2(b1.z, b1.w);
            float a[8] = {a0.x, a0.y, a0.z, a0.w, a1.x, a1.y, a1.z, a1.w};
            #pragma unroll
            for (int i = 0; i < 8; i++) {
                ull ap = pack2(a[i], a[i]);
                fma2(acc[i][0], ap, bb0);
                fma2(acc[i][1], ap, bb1);
                fma2(acc[i][2], ap, bb2);
                fma2(acc[i][3], ap, bb3);
            }
        }
        __syncthreads();
    }

    #pragma unroll
    for (int i = 0; i < 8; i++) {
        int r = m0 + cy * 8 + i;
        if (r < M) {
            float di = SCALE ? g_dinv[r] : 1.0f;
            float2 p0 = unpack2(acc[i][0]);
            float2 p1 = unpack2(acc[i][1]);
            float2 p2 = unpack2(acc[i][2]);
            float2 p3 = unpack2(acc[i][3]);
            float4 o0, o1;
            if (SCALE) {
                o0 = make_float4(di * p0.x, di * p0.y, di * p1.x, di * p1.y);
                o1 = make_float4(di * p2.x, di * p2.y, di * p3.x, di * p3.y);
            } else {
                o0 = make_float4(p0.x, p0.y, p1.x, p1.y);
                o1 = make_float4(p2.x, p2.y, p3.x, p3.y);
            }
            *(float4*)(out + (size_t)r * BN + cx * 8) = o0;
            *(float4*)(out + (size_t)r * BN + cx * 8 + 4) = o1;
        }
    }
}

// ---------------- layer-1 aggregation: warp per node, F=128, ReLU ----------
// xws is UNSCALED; each gathered row is weighted by dinv[src] via FFMA.
__global__ __launch_bounds__(256)
void agg1_kernel(const float* __restrict__ xws, const float* __restrict__ bias,
                 float* __restrict__ out, int M) {
    int node = blockIdx.x * 8 + (threadIdx.x >> 5);
    if (node >= M) return;
    int lane = threadIdx.x & 31;
    const float4* base = (const float4*)xws;
    size_t off = (size_t)node * 32 + lane;
    float dnode = g_dinv[node];
    float4 self = __ldg(base + off);
    float4 a0, a1, a2, a3;
    a0.x = dnode * self.x; a0.y = dnode * self.y;
    a0.z = dnode * self.z; a0.w = dnode * self.w;           // self loop
    a1 = make_float4(0.f, 0.f, 0.f, 0.f);
    a2 = make_float4(0.f, 0.f, 0.f, 0.f);
    a3 = make_float4(0.f, 0.f, 0.f, 0.f);
    int s = g_rowptr[node], e = g_rowptr[node + 1];

    for (int cs = s; cs < e; cs += 32) {
        int cnt = e - cs; if (cnt > 32) cnt = 32;
        int idx = 0; float dv = 0.f;
        if (cs + lane < e) {
            idx = g_colidx[cs + lane];
            dv = g_dinv[idx];
        }
        int j = 0;
        for (; j + 4 <= cnt; j += 4) {
            int s0 = __shfl_sync(0xffffffffu, idx, j);
            int s1 = __shfl_sync(0xffffffffu, idx, j + 1);
            int s2 = __shfl_sync(0xffffffffu, idx, j + 2);
            int s3 = __shfl_sync(0xffffffffu, idx, j + 3);
            float d0 = __shfl_sync(0xffffffffu, dv, j);
            float d1 = __shfl_sync(0xffffffffu, dv, j + 1);
            float d2 = __shfl_sync(0xffffffffu, dv, j + 2);
            float d3 = __shfl_sync(0xffffffffu, dv, j + 3);
            float4 v0 = __ldg(base + (size_t)s0 * 32 + lane);
            float4 v1 = __ldg(base + (size_t)s1 * 32 + lane);
            float4 v2 = __ldg(base + (size_t)s2 * 32 + lane);
            float4 v3 = __ldg(base + (size_t)s3 * 32 + lane);
            a0.x = fmaf(v0.x, d0, a0.x); a0.y = fmaf(v0.y, d0, a0.y);
            a0.z = fmaf(v0.z, d0, a0.z); a0.w = fmaf(v0.w, d0, a0.w);
            a1.x = fmaf(v1.x, d1, a1.x); a1.y = fmaf(v1.y, d1, a1.y);
            a1.z = fmaf(v1.z, d1, a1.z); a1.w = fmaf(v1.w, d1, a1.w);
            a2.x = fmaf(v2.x, d2, a2.x); a2.y = fmaf(v2.y, d2, a2.y);
            a2.z = fmaf(v2.z, d2, a2.z); a2.w = fmaf(v2.w, d2, a2.w);
            a3.x = fmaf(v3.x, d3, a3.x); a3.y = fmaf(v3.y, d3, a3.y);
            a3.z = fmaf(v3.z, d3, a3.z); a3.w = fmaf(v3.w, d3, a3.w);
        }
        for (; j < cnt; j++) {
            int s0 = __shfl_sync(0xffffffffu, idx, j);
            float d0 = __shfl_sync(0xffffffffu, dv, j);
            float4 v0 = __ldg(base + (size_t)s0 * 32 + lane);
            a1.x = fmaf(v0.x, d0, a1.x); a1.y = fmaf(v0.y, d0, a1.y);
            a1.z = fmaf(v0.z, d0, a1.z); a1.w = fmaf(v0.w, d0, a1.w);
        }
    }
    float4 acc;
    acc.x = (a0.x + a1.x) + (a2.x + a3.x);
    acc.y = (a0.y + a1.y) + (a2.y + a3.y);
    acc.z = (a0.z + a1.z) + (a2.z + a3.z);
    acc.w = (a0.w + a1.w) + (a2.w + a3.w);
    float4 bv = __ldg((const float4*)bias + lane);
    float4 r;
    r.x = fmaxf(fmaf(dnode, acc.x, bv.x), 0.0f);
    r.y = fmaxf(fmaf(dnode, acc.y, bv.y), 0.0f);
    r.z = fmaxf(fmaf(dnode, acc.z, bv.z), 0.0f);
    r.w = fmaxf(fmaf(dnode, acc.w, bv.w), 0.0f);
    ((float4*)out)[off] = r;
}

// ---------------- layer-2 aggregation + fused mean-pool (sums) -------------
// xws2 IS pre-scaled by dinv (gemm2 epilogue).
__global__ __launch_bounds__(256)
void agg2_pool_kernel(const float* __restrict__ xws, const float* __restrict__ bias,
                      int M) {
    __shared__ float spool[64 * 64];
    __shared__ int s_gmin, s_gmax;
    int tid = threadIdx.x;
    for (int j = tid; j < 64 * 64; j += 256) spool[j] = 0.0f;
    if (tid == 0) { s_gmin = 1 << 30; s_gmax = -1; }
    __syncthreads();

    int node = blockIdx.x * 8 + (tid >> 5);
    int lane = tid & 31;
    if (node < M) {
        const float2* base = (const float2*)xws;
        size_t off = (size_t)node * 32 + lane;
        float2 a0 = __ldg(base + off);       // self loop
        float2 a1 = make_float2(0.f, 0.f);
        float2 a2 = make_float2(0.f, 0.f);
        float2 a3 = make_float2(0.f, 0.f);
        int s = g_rowptr[node], e = g_rowptr[node + 1];
        for (int cs = s; cs < e; cs += 32) {
            int cnt = e - cs; if (cnt > 32) cnt = 32;
            int idx = (cs + lane < e) ? g_colidx[cs + lane] : 0;
            int j = 0;
            for (; j + 4 <= cnt; j += 4) {
                int s0 = __shfl_sync(0xffffffffu, idx, j);
                int s1 = __shfl_sync(0xffffffffu, idx, j + 1);
                int s2 = __shfl_sync(0xffffffffu, idx, j + 2);
                int s3 = __shfl_sync(0xffffffffu, idx, j + 3);
                float2 v0 = __ldg(base + (size_t)s0 * 32 + lane);
                float2 v1 = __ldg(base + (size_t)s1 * 32 + lane);
                float2 v2 = __ldg(base + (size_t)s2 * 32 + lane);
                float2 v3 = __ldg(base + (size_t)s3 * 32 + lane);
                a0.x += v0.x; a0.y += v0.y;
                a1.x += v1.x; a1.y += v1.y;
                a2.x += v2.x; a2.y += v2.y;
                a3.x += v3.x; a3.y += v3.y;
            }
            for (; j < cnt; j++) {
                int s0 = __shfl_sync(0xffffffffu, idx, j);
                float2 v0 = __ldg(base + (size_t)s0 * 32 + lane);
                a1.x += v0.x; a1.y += v0.y;
            }
        }
        float accx = (a0.x + a1.x) + (a2.x + a3.x);
        float accy = (a0.y + a1.y) + (a2.y + a3.y);
        float di = g_dinv[node];
        float2 bv = __ldg((const float2*)bias + lane);
        float rx = fmaf(di, accx, bv.x);
        float ry = fmaf(di, accy, bv.y);
        int g = g_batch[node];
        if (lane == 0) { atomicMin(&s_gmin, g); atomicMax(&s_gmax, g); }
        atomicAdd(&spool[g * 64 + lane * 2], rx);
        atomicAdd(&spool[g * 64 + lane * 2 + 1], ry);
    }
    __syncthreads();
    int gmin = s_gmin, gmax = s_gmax;
    if (gmax >= gmin) {
        int lo = gmin * 64;
        int cnt = (gmax - gmin + 1) * 64;
        for (int j = tid; j < cnt; j += 256)
            atomicAdd(&g_gsum[lo + j], spool[lo + j]);
    }
}

__global__ void k_final(float* __restrict__ out, int n) {
    int i = blockIdx.x * blockDim.x + threadIdx.x;
    if (i < n) out[i] = g_gsum[i] / fmaxf(g_gcnt[i >> 6], 1.0f);
}

// ---------------- launch ----------------------------------------------------
extern "C" void kernel_launch(void* const* d_in, const int* in_sizes, int n_in,
                              void* d_out, int out_size) {
    const float* x  = (const float*)d_in[0];
    const void*  ei = d_in[1];
    const void*  bp = d_in[2];
    const float* W1 = (const float*)d_in[3];
    const float* b1 = (const float*)d_in[4];
    const float* W2 = (const float*)d_in[5];
    const float* b2 = (const float*)d_in[6];
    float* out = (float*)d_out;

    int N    = in_sizes[2];          // 50000
    int E    = in_sizes[1] / 2;      // 800000
    int din  = in_sizes[0] / N;      // 128
    int dhid = in_sizes[4];          // 128
    int NG   = out_size / in_sizes[6];
    (void)NG;

    float *p_xws1, *p_h, *p_xws2;
    cudaGetSymbolAddress((void**)&p_xws1, g_xws1);
    cudaGetSymbolAddress((void**)&p_h,    g_h);
    cudaGetSymbolAddress((void**)&p_xws2, g_xws2);

    // One-time side-stream + events for fork/join graph branches.
    static cudaStream_t s2 = nullptr;
    static cudaEvent_t ev_fork = nullptr, ev_join = nullptr;
    if (s2 == nullptr) {
        cudaStreamCreateWithFlags(&s2, cudaStreamNonBlocking);
        cudaEventCreateWithFlags(&ev_fork, cudaEventDisableTiming);
        cudaEventCreateWithFlags(&ev_join, cudaEventDisableTiming);
    }

    int nbE = (E + 255) / 256;
    int nbI = ((N > 4096 ? N : 4096) + 255) / 256;

    // ---- init (both branches depend on it) ----
    k_init_detect<<<nbI, 256>>>(N, ei);

    // ---- fork: branch B = gemm1 (independent of graph structure) ----
    cudaEventRecord(ev_fork, 0);
    cudaStreamWaitEvent(s2, ev_fork, 0);
    gemm_kernel<128, 256, false><<<(N + 127) / 128, 256, 0, s2>>>(x, W1, p_xws1, N, din);
    cudaEventRecord(ev_join, s2);

    // ---- branch A: CSR build on main stream ----
    k_conv_fused<<<nbE, 256>>>(ei, bp, E, N, NG > 64 ? 64 : NG);
    k_scan1<<<1, 1024>>>(N);
    k_fill<<<nbE, 256>>>(E);

    // ---- join ----
    cudaStreamWaitEvent(0, ev_join, 0);

    // layer 1 aggregation (applies dinv[src] and dinv[dst])
    agg1_kernel<<<(N + 7) / 8, 256>>>(p_xws1, b1, p_h, N);

    // layer 2 + fused pooling
    gemm_kernel<64, 128, true><<<(N + 127) / 128, 128>>>(p_h, W2, p_xws2, N, dhid);
    agg2_pool_kernel<<<(N + 7) / 8, 256>>>(p_xws2, b2, N);

    k_final<<<(out_size + 255) / 256, 256>>>(out, out_size);
}

// round 8
// speedup vs baseline: 1.4282x; 1.4282x over previous
#include <cuda_runtime.h>
#include <cuda_bf16.h>

typedef unsigned long long ull;

// Problem-fixed capacities (N=50000, E=800000, d_hid=128, d_out=64, 64 graphs)
#define MAXN 50000
#define MAXE 800000
#define SCAN_CHUNK 512

// ---------------- scratch (device globals; no runtime allocation) ----------
__device__ float g_xws1[MAXN * 128];   // x @ W1 (UNSCALED)
__device__ float g_h[MAXN * 128];      // relu layer-1 output
__device__ float g_xws2[MAXN * 64];    // dinv * (h @ W2)
__device__ float g_dinv[MAXN];
__device__ int   g_cnt[MAXN];
__device__ int   g_cursor[MAXN];
__device__ int   g_rowptr[MAXN + 1];
__device__ int   g_colidx[MAXE];
__device__ int   g_src[MAXE];
__device__ int   g_dst[MAXE];
__device__ int   g_batch[MAXN];
__device__ float g_gsum[64 * 64];
__device__ float g_gcnt[64];
__device__ int   g_flag64;
__device__ int   g_bsum[128];
__device__ int   g_boff[128];

// ---------------- f32x2 helpers (packed fp32 FMA, sm_100+) -----------------
__device__ __forceinline__ ull pack2(float a, float b) {
    ull r;
    asm("mov.b64 %0, {%1, %2};" : "=l"(r) : "f"(a), "f"(b));
    return r;
}
__device__ __forceinline__ float2 unpack2(ull v) {
    float2 r;
    asm("mov.b64 {%0, %1}, %2;" : "=f"(r.x), "=f"(r.y) : "l"(v));
    return r;
}
__device__ __forceinline__ void fma2(ull& d, ull a, ull b) {
    asm("fma.rn.f32x2 %0, %1, %2, %0;" : "+l"(d) : "l"(a), "l"(b));
}

// ---------------- setup: init scratch + dtype detect (fused) ---------------
__global__ void k_init_detect(int N, const void* edges) {
    int i = blockIdx.x * blockDim.x + threadIdx.x;
    if (i < N) { g_cnt[i] = 0; g_cursor[i] = 0; }
    if (i < 64 * 64) g_gsum[i] = 0.0f;
    if (i < 64) g_gcnt[i] = 0.0f;
    if (i == 0) {
        const long long* p = (const long long*)edges;
        long long v[8];
        #pragma unroll
        for (int k = 0; k < 8; k++) v[k] = p[k];
        int ok = 1;
        #pragma unroll
        for (int k = 0; k < 8; k++)
            if (v[k] < 0 || v[k] > 0x7fffffffLL) ok = 0;
        g_flag64 = ok;
    }
}

// Fused: edge conversion + degree count + batch conversion + graph-size hist.
__global__ void k_conv_fused(const void* edges, const void* bp,
                             int E, int N, int NG) {
    __shared__ int sh[64];
    int tid = threadIdx.x;
    if (tid < 64) sh[tid] = 0;
    __syncthreads();
    int e = blockIdx.x * blockDim.x + tid;
    int f64 = g_flag64;
    if (e < E) {
        long long s, d;
        if (f64) {
            const long long* p = (const long long*)edges;
            s = p[e]; d = p[(size_t)E + e];
        } else {
            const int* p = (const int*)edges;
            s = p[e]; d = p[E + e];
        }
        if (s < 0) s = 0; if (s >= N) s = N - 1;
        if (d < 0) d = 0; if (d >= N) d = N - 1;
        g_src[e] = (int)s;
        g_dst[e] = (int)d;
        atomicAdd(&g_cnt[(int)d], 1);
    }
    if (e < N) {
        long long b;
        if (f64) b = ((const long long*)bp)[e];
        else     b = ((const int*)bp)[e];
        if (b < 0) b = 0; if (b >= NG) b = NG - 1;
        g_batch[e] = (int)b;
        atomicAdd(&sh[(int)b], 1);
    }
    __syncthreads();
    if (tid < 64 && sh[tid] != 0)
        atomicAdd(&g_gcnt[tid], (float)sh[tid]);
}

// ---------------- 3-phase parallel scan over g_cnt -> g_rowptr -------------
__global__ void k_scanA(int n) {   // per-block partial sums (coalesced)
    __shared__ int ws[16];
    int tid = threadIdx.x, lane = tid & 31, wid = tid >> 5;
    int i = blockIdx.x * SCAN_CHUNK + tid;
    int v = (i < n) ? g_cnt[i] : 0;
    #pragma unroll
    for (int o = 16; o; o >>= 1) v += __shfl_down_sync(0xffffffffu, v, o);
    if (lane == 0) ws[wid] = v;
    __syncthreads();
    if (wid == 0) {
        int t = (lane < 16) ? ws[lane] : 0;
        #pragma unroll
        for (int o = 16; o; o >>= 1) t += __shfl_down_sync(0xffffffffu, t, o);
        if (lane == 0) g_bsum[blockIdx.x] = t;
    }
}

__global__ void k_scanB(int nb) {  // exclusive scan of <=128 partials
    __shared__ int ws[4];
    __shared__ int woff[4];
    int tid = threadIdx.x, lane = tid & 31, wid = tid >> 5;
    int v = (tid < nb) ? g_bsum[tid] : 0;
    int incl = v;
    #pragma unroll
    for (int o = 1; o < 32; o <<= 1) {
        int t = __shfl_up_sync(0xffffffffu, incl, o);
        if (lane >= o) incl += t;
    }
    if (lane == 31) ws[wid] = incl;
    __syncthreads();
    if (tid == 0) {
        int acc = 0;
        #pragma unroll
        for (int w = 0; w < 4; w++) { woff[w] = acc; acc += ws[w]; }
    }
    __syncthreads();
    if (tid < nb) g_boff[tid] = incl - v + woff[wid];
}

__global__ void k_scanC(int n) {   // final coalesced scan + dinv fused
    __shared__ int ws[16];
    __shared__ int woff[16];
    int tid = threadIdx.x, lane = tid & 31, wid = tid >> 5;
    int i = blockIdx.x * SCAN_CHUNK + tid;
    int v = (i < n) ? g_cnt[i] : 0;
    int incl = v;
    #pragma unroll
    for (int o = 1; o < 32; o <<= 1) {
        int t = __shfl_up_sync(0xffffffffu, incl, o);
        if (lane >= o) incl += t;
    }
    if (lane == 31) ws[wid] = incl;
    __syncthreads();
    if (wid == 0 && lane < 16) {
        int w = ws[lane];
        int wincl = w;
        #pragma unroll
        for (int o = 1; o < 16; o <<= 1) {
            int t = __shfl_up_sync(0x0000ffffu, wincl, o);
            if (lane >= o) wincl += t;
        }
        woff[lane] = wincl - w;
    }
    __syncthreads();
    int excl = (incl - v) + woff[wid] + g_boff[blockIdx.x];
    if (i < n) {
        g_rowptr[i] = excl;
        g_dinv[i] = rsqrtf((float)v + 1.0f);   // +1 self loop
    }
    if (i == n - 1) g_rowptr[n] = excl + v;
}

__global__ void k_fill(int E) {
    int e = blockIdx.x * blockDim.x + threadIdx.x;
    if (e >= E) return;
    int d = g_dst[e];
    int pos = atomicAdd(&g_cursor[d], 1);
    g_colidx[g_rowptr[d] + pos] = g_src[e];
}

// ---------------- GEMM: out[m][:] = (dinv[m]?) * (X[m][:] @ W) -------------
template <int BN, int NT, bool SCALE>
__global__ __launch_bounds__(NT, 1)
void gemm_kernel(const float* __restrict__ X, const float* __restrict__ W,
                 float* __restrict__ out, int M, int K) {
    constexpr int BM = 128, BK = 32;
    __shared__ float xs[BK][BM + 4];
    __shared__ float ws[BK][BN];

    int tid = threadIdx.x;
    int cx = tid % (BN / 8);
    int cy = tid / (BN / 8);
    int m0 = blockIdx.x * BM;

    ull acc[8][4];
    #pragma unroll
    for (int i = 0; i < 8; i++)
        #pragma unroll
        for (int j = 0; j < 4; j++) acc[i][j] = 0ull;

    for (int kt = 0; kt < K; kt += BK) {
        #pragma unroll
        for (int l = 0; l < (BM * BK / 4) / NT; l++) {
            int idx = tid + l * NT;
            int r = idx >> 3;
            int kq = idx & 7;
            int grow = m0 + r;
            if (grow >= M) grow = M - 1;
            float4 v = __ldg((const float4*)(X + (size_t)grow * K + kt + kq * 4));
            xs[kq * 4 + 0][r] = v.x;
            xs[kq * 4 + 1][r] = v.y;
            xs[kq * 4 + 2][r] = v.z;
            xs[kq * 4 + 3][r] = v.w;
        }
        #pragma unroll
        for (int l = 0; l < (BK * BN / 4) / NT; l++) {
            int idx = tid + l * NT;
            int wr = idx / (BN / 4);
            int wc = idx % (BN / 4);
            float4 v = __ldg((const float4*)(W + (size_t)(kt + wr) * BN + wc * 4));
            *(float4*)&ws[wr][wc * 4] = v;
        }
        __syncthreads();

        #pragma unroll
        for (int kk = 0; kk < BK; kk++) {
            float4 a0 = *(const float4*)&xs[kk][cy * 8];
            float4 a1 = *(const float4*)&xs[kk][cy * 8 + 4];
            float4 b0 = *(const float4*)&ws[kk][cx * 8];
            float4 b1 = *(const float4*)&ws[kk][cx * 8 + 4];
            ull bb0 = pack2(b0.x, b0.y), bb1 = pack2(b0.z, b0.w);
            ull bb2 = pack2(b1.x, b1.y), bb3 = pack2(b1.z, b1.w);
            float a[8] = {a0.x, a0.y, a0.z, a0.w, a1.x, a1.y, a1.z, a1.w};
            #pragma unroll
            for (int i = 0; i < 8; i++) {
                ull ap = pack2(a[i], a[i]);
                fma2(acc[i][0], ap, bb0);
                fma2(acc[i][1], ap, bb1);
                fma2(acc[i][2], ap, bb2);
                fma2(acc[i][3], ap, bb3);
            }
        }
        __syncthreads();
    }

    #pragma unroll
    for (int i = 0; i < 8; i++) {
        int r = m0 + cy * 8 + i;
        if (r < M) {
            float di = SCALE ? g_dinv[r] : 1.0f;
            float2 p0 = unpack2(acc[i][0]);
            float2 p1 = unpack2(acc[i][1]);
            float2 p2 = unpack2(acc[i][2]);
            float2 p3 = unpack2(acc[i][3]);
            float4 o0, o1;
            if (SCALE) {
                o0 = make_float4(di * p0.x, di * p0.y, di * p1.x, di * p1.y);
                o1 = make_float4(di * p2.x, di * p2.y, di * p3.x, di * p3.y);
            } else {
                o0 = make_float4(p0.x, p0.y, p1.x, p1.y);
                o1 = make_float4(p2.x, p2.y, p3.x, p3.y);
            }
            *(float4*)(out + (size_t)r * BN + cx * 8) = o0;
            *(float4*)(out + (size_t)r * BN + cx * 8 + 4) = o1;
        }
    }
}

// ---------------- layer-1 aggregation: warp per node, F=128, ReLU ----------
// xws is UNSCALED; each gathered row is weighted by dinv[src] via FFMA.
__global__ __launch_bounds__(256)
void agg1_kernel(const float* __restrict__ xws, const float* __restrict__ bias,
                 float* __restrict__ out, int M) {
    int node = blockIdx.x * 8 + (threadIdx.x >> 5);
    if (node >= M) return;
    int lane = threadIdx.x & 31;
    const float4* base = (const float4*)xws;
    size_t off = (size_t)node * 32 + lane;
    float dnode = g_dinv[node];
    float4 self = __ldg(base + off);
    float4 a0, a1, a2, a3;
    a0.x = dnode * self.x; a0.y = dnode * self.y;
    a0.z = dnode * self.z; a0.w = dnode * self.w;           // self loop
    a1 = make_float4(0.f, 0.f, 0.f, 0.f);
    a2 = make_float4(0.f, 0.f, 0.f, 0.f);
    a3 = make_float4(0.f, 0.f, 0.f, 0.f);
    int s = g_rowptr[node], e = g_rowptr[node + 1];

    for (int cs = s; cs < e; cs += 32) {
        int cnt = e - cs; if (cnt > 32) cnt = 32;
        int idx = 0; float dv = 0.f;
        if (cs + lane < e) {
            idx = g_colidx[cs + lane];
            dv = g_dinv[idx];
        }
        int j = 0;
        for (; j + 4 <= cnt; j += 4) {
            int s0 = __shfl_sync(0xffffffffu, idx, j);
            int s1 = __shfl_sync(0xffffffffu, idx, j + 1);
            int s2 = __shfl_sync(0xffffffffu, idx, j + 2);
            int s3 = __shfl_sync(0xffffffffu, idx, j + 3);
            float d0 = __shfl_sync(0xffffffffu, dv, j);
            float d1 = __shfl_sync(0xffffffffu, dv, j + 1);
            float d2 = __shfl_sync(0xffffffffu, dv, j + 2);
            float d3 = __shfl_sync(0xffffffffu, dv, j + 3);
            float4 v0 = __ldg(base + (size_t)s0 * 32 + lane);
            float4 v1 = __ldg(base + (size_t)s1 * 32 + lane);
            float4 v2 = __ldg(base + (size_t)s2 * 32 + lane);
            float4 v3 = __ldg(base + (size_t)s3 * 32 + lane);
            a0.x = fmaf(v0.x, d0, a0.x); a0.y = fmaf(v0.y, d0, a0.y);
            a0.z = fmaf(v0.z, d0, a0.z); a0.w = fmaf(v0.w, d0, a0.w);
            a1.x = fmaf(v1.x, d1, a1.x); a1.y = fmaf(v1.y, d1, a1.y);
            a1.z = fmaf(v1.z, d1, a1.z); a1.w = fmaf(v1.w, d1, a1.w);
            a2.x = fmaf(v2.x, d2, a2.x); a2.y = fmaf(v2.y, d2, a2.y);
            a2.z = fmaf(v2.z, d2, a2.z); a2.w = fmaf(v2.w, d2, a2.w);
            a3.x = fmaf(v3.x, d3, a3.x); a3.y = fmaf(v3.y, d3, a3.y);
            a3.z = fmaf(v3.z, d3, a3.z); a3.w = fmaf(v3.w, d3, a3.w);
        }
        for (; j < cnt; j++) {
            int s0 = __shfl_sync(0xffffffffu, idx, j);
            float d0 = __shfl_sync(0xffffffffu, dv, j);
            float4 v0 = __ldg(base + (size_t)s0 * 32 + lane);
            a1.x = fmaf(v0.x, d0, a1.x); a1.y = fmaf(v0.y, d0, a1.y);
            a1.z = fmaf(v0.z, d0, a1.z); a1.w = fmaf(v0.w, d0, a1.w);
        }
    }
    float4 acc;
    acc.x = (a0.x + a1.x) + (a2.x + a3.x);
    acc.y = (a0.y + a1.y) + (a2.y + a3.y);
    acc.z = (a0.z + a1.z) + (a2.z + a3.z);
    acc.w = (a0.w + a1.w) + (a2.w + a3.w);
    float4 bv = __ldg((const float4*)bias + lane);
    float4 r;
    r.x = fmaxf(fmaf(dnode, acc.x, bv.x), 0.0f);
    r.y = fmaxf(fmaf(dnode, acc.y, bv.y), 0.0f);
    r.z = fmaxf(fmaf(dnode, acc.z, bv.z), 0.0f);
    r.w = fmaxf(fmaf(dnode, acc.w, bv.w), 0.0f);
    ((float4*)out)[off] = r;
}

// ---------------- layer-2 aggregation + fused mean-pool (sums) -------------
// xws2 IS pre-scaled by dinv (gemm2 epilogue).
__global__ __launch_bounds__(256)
void agg2_pool_kernel(const float* __restrict__ xws, const float* __restrict__ bias,
                      int M) {
    __shared__ float spool[64 * 64];
    __shared__ int s_gmin, s_gmax;
    int tid = threadIdx.x;
    for (int j = tid; j < 64 * 64; j += 256) spool[j] = 0.0f;
    if (tid == 0) { s_gmin = 1 << 30; s_gmax = -1; }
    __syncthreads();

    int node = blockIdx.x * 8 + (tid >> 5);
    int lane = tid & 31;
    if (node < M) {
        const float2* base = (const float2*)xws;
        size_t off = (size_t)node * 32 + lane;
        float2 a0 = __ldg(base + off);       // self loop
        float2 a1 = make_float2(0.f, 0.f);
        float2 a2 = make_float2(0.f, 0.f);
        float2 a3 = make_float2(0.f, 0.f);
        int s = g_rowptr[node], e = g_rowptr[node + 1];
        for (int cs = s; cs < e; cs += 32) {
            int cnt = e - cs; if (cnt > 32) cnt = 32;
            int idx = (cs + lane < e) ? g_colidx[cs + lane] : 0;
            int j = 0;
            for (; j + 4 <= cnt; j += 4) {
                int s0 = __shfl_sync(0xffffffffu, idx, j);
                int s1 = __shfl_sync(0xffffffffu, idx, j + 1);
                int s2 = __shfl_sync(0xffffffffu, idx, j + 2);
                int s3 = __shfl_sync(0xffffffffu, idx, j + 3);
                float2 v0 = __ldg(base + (size_t)s0 * 32 + lane);
                float2 v1 = __ldg(base + (size_t)s1 * 32 + lane);
                float2 v2 = __ldg(base + (size_t)s2 * 32 + lane);
                float2 v3 = __ldg(base + (size_t)s3 * 32 + lane);
                a0.x += v0.x; a0.y += v0.y;
                a1.x += v1.x; a1.y += v1.y;
                a2.x += v2.x; a2.y += v2.y;
                a3.x += v3.x; a3.y += v3.y;
            }
            for (; j < cnt; j++) {
                int s0 = __shfl_sync(0xffffffffu, idx, j);
                float2 v0 = __ldg(base + (size_t)s0 * 32 + lane);
                a1.x += v0.x; a1.y += v0.y;
            }
        }
        float accx = (a0.x + a1.x) + (a2.x + a3.x);
        float accy = (a0.y + a1.y) + (a2.y + a3.y);
        float di = g_dinv[node];
        float2 bv = __ldg((const float2*)bias + lane);
        float rx = fmaf(di, accx, bv.x);
        float ry = fmaf(di, accy, bv.y);
        int g = g_batch[node];
        if (lane == 0) { atomicMin(&s_gmin, g); atomicMax(&s_gmax, g); }
        atomicAdd(&spool[g * 64 + lane * 2], rx);
        atomicAdd(&spool[g * 64 + lane * 2 + 1], ry);
    }
    __syncthreads();
    int gmin = s_gmin, gmax = s_gmax;
    if (gmax >= gmin) {
        int lo = gmin * 64;
        int cnt = (gmax - gmin + 1) * 64;
        for (int j = tid; j < cnt; j += 256)
            atomicAdd(&g_gsum[lo + j], spool[lo + j]);
    }
}

__global__ void k_final(float* __restrict__ out, int n) {
    int i = blockIdx.x * blockDim.x + threadIdx.x;
    if (i < n) out[i] = g_gsum[i] / fmaxf(g_gcnt[i >> 6], 1.0f);
}

// ---------------- launch ----------------------------------------------------
extern "C" void kernel_launch(void* const* d_in, const int* in_sizes, int n_in,
                              void* d_out, int out_size) {
    const float* x  = (const float*)d_in[0];
    const void*  ei = d_in[1];
    const void*  bp = d_in[2];
    const float* W1 = (const float*)d_in[3];
    const float* b1 = (const float*)d_in[4];
    const float* W2 = (const float*)d_in[5];
    const float* b2 = (const float*)d_in[6];
    float* out = (float*)d_out;

    int N    = in_sizes[2];          // 50000
    int E    = in_sizes[1] / 2;      // 800000
    int din  = in_sizes[0] / N;      // 128
    int dhid = in_sizes[4];          // 128
    int NG   = out_size / in_sizes[6];

    float *p_xws1, *p_h, *p_xws2;
    cudaGetSymbolAddress((void**)&p_xws1, g_xws1);
    cudaGetSymbolAddress((void**)&p_h,    g_h);
    cudaGetSymbolAddress((void**)&p_xws2, g_xws2);

    // One-time side-stream + events for fork/join graph branches.
    static cudaStream_t s2 = nullptr;
    static cudaEvent_t ev_fork = nullptr, ev_join = nullptr;
    if (s2 == nullptr) {
        cudaStreamCreateWithFlags(&s2, cudaStreamNonBlocking);
        cudaEventCreateWithFlags(&ev_fork, cudaEventDisableTiming);
        cudaEventCreateWithFlags(&ev_join, cudaEventDisableTiming);
    }

    int nbE = (E + 255) / 256;
    int nbI = ((N > 4096 ? N : 4096) + 255) / 256;
    int nbS = (N + SCAN_CHUNK - 1) / SCAN_CHUNK;

    // ---- init (both branches depend on it) ----
    k_init_detect<<<nbI, 256>>>(N, ei);

    // ---- fork: branch B = gemm1 (independent of graph structure) ----
    cudaEventRecord(ev_fork, 0);
    cudaStreamWaitEvent(s2, ev_fork, 0);
    gemm_kernel<128, 256, false><<<(N + 127) / 128, 256, 0, s2>>>(x, W1, p_xws1, N, din);
    cudaEventRecord(ev_join, s2);

    // ---- branch A: CSR build on main stream ----
    k_conv_fused<<<nbE, 256>>>(ei, bp, E, N, NG > 64 ? 64 : NG);
    k_scanA<<<nbS, SCAN_CHUNK>>>(N);
    k_scanB<<<1, 128>>>(nbS);
    k_scanC<<<nbS, SCAN_CHUNK>>>(N);
    k_fill<<<nbE, 256>>>(E);

    // ---- join ----
    cudaStreamWaitEvent(0, ev_join, 0);

    // layer 1 aggregation (applies dinv[src] and dinv[dst])
    agg1_kernel<<<(N + 7) / 8, 256>>>(p_xws1, b1, p_h, N);

    // layer 2 + fused pooling
    gemm_kernel<64, 128, true><<<(N + 127) / 128, 128>>>(p_h, W2, p_xws2, N, dhid);
    agg2_pool_kernel<<<(N + 7) / 8, 256>>>(p_xws2, b2, N);

    k_final<<<(out_size + 255) / 256, 256>>>(out, out_size);
}

// round 9
// speedup vs baseline: 1.5706x; 1.0997x over previous
#include <cuda_runtime.h>
#include <cuda_bf16.h>
#include <cuda_fp16.h>

typedef unsigned long long ull;

// Problem-fixed capacities (N=50000, E=800000, d_hid=128, d_out=64, 64 graphs)
#define MAXN 50000
#define MAXE 800000
#define SCAN_CHUNK 512

// ---------------- scratch (device globals; no runtime allocation) ----------
__device__ __half g_xws1h[MAXN * 128]; // x @ W1 (UNSCALED), fp16 gather table
__device__ float  g_h[MAXN * 128];     // relu layer-1 output (fp32, gemm2 input)
__device__ __half g_xws2h[MAXN * 64];  // dinv * (h @ W2), fp16 gather table
__device__ float  g_dinv[MAXN];
__device__ int    g_cnt[MAXN];
__device__ int    g_cursor[MAXN];
__device__ int    g_rowptr[MAXN + 1];
__device__ int    g_colidx[MAXE];
__device__ int    g_src[MAXE];
__device__ int    g_dst[MAXE];
__device__ int    g_batch[MAXN];
__device__ float  g_gsum[64 * 64];
__device__ float  g_gcnt[64];
__device__ int    g_flag64;
__device__ int    g_bsum[128];
__device__ int    g_boff[128];

// ---------------- f32x2 helpers (packed fp32 FMA, sm_100+) -----------------
__device__ __forceinline__ ull pack2(float a, float b) {
    ull r;
    asm("mov.b64 %0, {%1, %2};" : "=l"(r) : "f"(a), "f"(b));
    return r;
}
__device__ __forceinline__ float2 unpack2(ull v) {
    float2 r;
    asm("mov.b64 {%0, %1}, %2;" : "=f"(r.x), "=f"(r.y) : "l"(v));
    return r;
}
__device__ __forceinline__ void fma2(ull& d, ull a, ull b) {
    asm("fma.rn.f32x2 %0, %1, %2, %0;" : "+l"(d) : "l"(a), "l"(b));
}

// ---------------- setup: init scratch + dtype detect (fused) ---------------
__global__ void k_init_detect(int N, const void* edges) {
    int i = blockIdx.x * blockDim.x + threadIdx.x;
    if (i < N) { g_cnt[i] = 0; g_cursor[i] = 0; }
    if (i < 64 * 64) g_gsum[i] = 0.0f;
    if (i < 64) g_gcnt[i] = 0.0f;
    if (i == 0) {
        const long long* p = (const long long*)edges;
        long long v[8];
        #pragma unroll
        for (int k = 0; k < 8; k++) v[k] = p[k];
        int ok = 1;
        #pragma unroll
        for (int k = 0; k < 8; k++)
            if (v[k] < 0 || v[k] > 0x7fffffffLL) ok = 0;
        g_flag64 = ok;
    }
}

// Fused: edge conversion + degree count + batch conversion + graph-size hist.
__global__ void k_conv_fused(const void* edges, const void* bp,
                             int E, int N, int NG) {
    __shared__ int sh[64];
    int tid = threadIdx.x;
    if (tid < 64) sh[tid] = 0;
    __syncthreads();
    int e = blockIdx.x * blockDim.x + tid;
    int f64 = g_flag64;
    if (e < E) {
        long long s, d;
        if (f64) {
            const long long* p = (const long long*)edges;
            s = p[e]; d = p[(size_t)E + e];
        } else {
            const int* p = (const int*)edges;
            s = p[e]; d = p[E + e];
        }
        if (s < 0) s = 0; if (s >= N) s = N - 1;
        if (d < 0) d = 0; if (d >= N) d = N - 1;
        g_src[e] = (int)s;
        g_dst[e] = (int)d;
        atomicAdd(&g_cnt[(int)d], 1);
    }
    if (e < N) {
        long long b;
        if (f64) b = ((const long long*)bp)[e];
        else     b = ((const int*)bp)[e];
        if (b < 0) b = 0; if (b >= NG) b = NG - 1;
        g_batch[e] = (int)b;
        atomicAdd(&sh[(int)b], 1);
    }
    __syncthreads();
    if (tid < 64 && sh[tid] != 0)
        atomicAdd(&g_gcnt[tid], (float)sh[tid]);
}

// ---------------- 3-phase parallel scan over g_cnt -> g_rowptr -------------
__global__ void k_scanA(int n) {
    __shared__ int ws[16];
    int tid = threadIdx.x, lane = tid & 31, wid = tid >> 5;
    int i = blockIdx.x * SCAN_CHUNK + tid;
    int v = (i < n) ? g_cnt[i] : 0;
    #pragma unroll
    for (int o = 16; o; o >>= 1) v += __shfl_down_sync(0xffffffffu, v, o);
    if (lane == 0) ws[wid] = v;
    __syncthreads();
    if (wid == 0) {
        int t = (lane < 16) ? ws[lane] : 0;
        #pragma unroll
        for (int o = 16; o; o >>= 1) t += __shfl_down_sync(0xffffffffu, t, o);
        if (lane == 0) g_bsum[blockIdx.x] = t;
    }
}

__global__ void k_scanB(int nb) {
    __shared__ int ws[4];
    __shared__ int woff[4];
    int tid = threadIdx.x, lane = tid & 31, wid = tid >> 5;
    int v = (tid < nb) ? g_bsum[tid] : 0;
    int incl = v;
    #pragma unroll
    for (int o = 1; o < 32; o <<= 1) {
        int t = __shfl_up_sync(0xffffffffu, incl, o);
        if (lane >= o) incl += t;
    }
    if (lane == 31) ws[wid] = incl;
    __syncthreads();
    if (tid == 0) {
        int acc = 0;
        #pragma unroll
        for (int w = 0; w < 4; w++) { woff[w] = acc; acc += ws[w]; }
    }
    __syncthreads();
    if (tid < nb) g_boff[tid] = incl - v + woff[wid];
}

__global__ void k_scanC(int n) {
    __shared__ int ws[16];
    __shared__ int woff[16];
    int tid = threadIdx.x, lane = tid & 31, wid = tid >> 5;
    int i = blockIdx.x * SCAN_CHUNK + tid;
    int v = (i < n) ? g_cnt[i] : 0;
    int incl = v;
    #pragma unroll
    for (int o = 1; o < 32; o <<= 1) {
        int t = __shfl_up_sync(0xffffffffu, incl, o);
        if (lane >= o) incl += t;
    }
    if (lane == 31) ws[wid] = incl;
    __syncthreads();
    if (wid == 0 && lane < 16) {
        int w = ws[lane];
        int wincl = w;
        #pragma unroll
        for (int o = 1; o < 16; o <<= 1) {
            int t = __shfl_up_sync(0x0000ffffu, wincl, o);
            if (lane >= o) wincl += t;
        }
        woff[lane] = wincl - w;
    }
    __syncthreads();
    int excl = (incl - v) + woff[wid] + g_boff[blockIdx.x];
    if (i < n) {
        g_rowptr[i] = excl;
        g_dinv[i] = rsqrtf((float)v + 1.0f);   // +1 self loop
    }
    if (i == n - 1) g_rowptr[n] = excl + v;
}

__global__ void k_fill(int E) {
    int e = blockIdx.x * blockDim.x + threadIdx.x;
    if (e >= E) return;
    int d = g_dst[e];
    int pos = atomicAdd(&g_cursor[d], 1);
    g_colidx[g_rowptr[d] + pos] = g_src[e];
}

// ---------------- GEMM: outh[m][:] = (dinv[m]?) * (X[m][:] @ W), fp16 out --
template <int BN, int NT, bool SCALE>
__global__ __launch_bounds__(NT, 1)
void gemm_kernel(const float* __restrict__ X, const float* __restrict__ W,
                 __half* __restrict__ outh, int M, int K) {
    constexpr int BM = 128, BK = 32;
    __shared__ float xs[BK][BM + 4];
    __shared__ float ws[BK][BN];

    int tid = threadIdx.x;
    int cx = tid % (BN / 8);
    int cy = tid / (BN / 8);
    int m0 = blockIdx.x * BM;

    ull acc[8][4];
    #pragma unroll
    for (int i = 0; i < 8; i++)
        #pragma unroll
        for (int j = 0; j < 4; j++) acc[i][j] = 0ull;

    for (int kt = 0; kt < K; kt += BK) {
        #pragma unroll
        for (int l = 0; l < (BM * BK / 4) / NT; l++) {
            int idx = tid + l * NT;
            int r = idx >> 3;
            int kq = idx & 7;
            int grow = m0 + r;
            if (grow >= M) grow = M - 1;
            float4 v = __ldg((const float4*)(X + (size_t)grow * K + kt + kq * 4));
            xs[kq * 4 + 0][r] = v.x;
            xs[kq * 4 + 1][r] = v.y;
            xs[kq * 4 + 2][r] = v.z;
            xs[kq * 4 + 3][r] = v.w;
        }
        #pragma unroll
        for (int l = 0; l < (BK * BN / 4) / NT; l++) {
            int idx = tid + l * NT;
            int wr = idx / (BN / 4);
            int wc = idx % (BN / 4);
            float4 v = __ldg((const float4*)(W + (size_t)(kt + wr) * BN + wc * 4));
            *(float4*)&ws[wr][wc * 4] = v;
        }
        __syncthreads();

        #pragma unroll
        for (int kk = 0; kk < BK; kk++) {
            float4 a0 = *(const float4*)&xs[kk][cy * 8];
            float4 a1 = *(const float4*)&xs[kk][cy * 8 + 4];
            float4 b0 = *(const float4*)&ws[kk][cx * 8];
            float4 b1 = *(const float4*)&ws[kk][cx * 8 + 4];
            ull bb0 = pack2(b0.x, b0.y), bb1 = pack2(b0.z, b0.w);
            ull bb2 = pack2(b1.x, b1.y), bb3 = pack2(b1.z, b1.w);
            float a[8] = {a0.x, a0.y, a0.z, a0.w, a1.x, a1.y, a1.z, a1.w};
            #pragma unroll
            for (int i = 0; i < 8; i++) {
                ull ap = pack2(a[i], a[i]);
                fma2(acc[i][0], ap, bb0);
                fma2(acc[i][1], ap, bb1);
                fma2(acc[i][2], ap, bb2);
                fma2(acc[i][3], ap, bb3);
            }
        }
        __syncthreads();
    }

    #pragma unroll
    for (int i = 0; i < 8; i++) {
        int r = m0 + cy * 8 + i;
        if (r < M) {
            float di = SCALE ? g_dinv[r] : 1.0f;
            float2 p0 = unpack2(acc[i][0]);
            float2 p1 = unpack2(acc[i][1]);
            float2 p2 = unpack2(acc[i][2]);
            float2 p3 = unpack2(acc[i][3]);
            __half2 h0 = __floats2half2_rn(di * p0.x, di * p0.y);
            __half2 h1 = __floats2half2_rn(di * p1.x, di * p1.y);
            __half2 h2 = __floats2half2_rn(di * p2.x, di * p2.y);
            __half2 h3 = __floats2half2_rn(di * p3.x, di * p3.y);
            uint4 o;
            o.x = *(unsigned*)&h0; o.y = *(unsigned*)&h1;
            o.z = *(unsigned*)&h2; o.w = *(unsigned*)&h3;
            *(uint4*)(outh + (size_t)r * BN + cx * 8) = o;   // 16B aligned
        }
    }
}

// ---------------- layer-1 aggregation: warp per node, F=128, ReLU ----------
// fp16 gather table; each gathered row weighted by dinv[src], fp32 accumulate.
__global__ __launch_bounds__(256)
void agg1_kernel(const __half* __restrict__ xws, const float* __restrict__ bias,
                 float* __restrict__ out, int M) {
    int node = blockIdx.x * 8 + (threadIdx.x >> 5);
    if (node >= M) return;
    int lane = threadIdx.x & 31;
    const uint2* b16 = (const uint2*)xws;     // 4 halfs per uint2; 32/row
    float dnode = g_dinv[node];

    uint2 sv = __ldg(b16 + (size_t)node * 32 + lane);
    __half2* sh = (__half2*)&sv;
    float2 sf0 = __half22float2(sh[0]);
    float2 sf1 = __half22float2(sh[1]);
    float4 a0, a1, a2, a3;
    a0.x = dnode * sf0.x; a0.y = dnode * sf0.y;
    a0.z = dnode * sf1.x; a0.w = dnode * sf1.y;          // self loop
    a1 = make_float4(0.f, 0.f, 0.f, 0.f);
    a2 = make_float4(0.f, 0.f, 0.f, 0.f);
    a3 = make_float4(0.f, 0.f, 0.f, 0.f);
    int s = g_rowptr[node], e = g_rowptr[node + 1];

    for (int cs = s; cs < e; cs += 32) {
        int cnt = e - cs; if (cnt > 32) cnt = 32;
        int idx = 0; float dv = 0.f;
        if (cs + lane < e) {
            idx = g_colidx[cs + lane];
            dv = g_dinv[idx];
        }
        int j = 0;
        for (; j + 4 <= cnt; j += 4) {
            int s0 = __shfl_sync(0xffffffffu, idx, j);
            int s1 = __shfl_sync(0xffffffffu, idx, j + 1);
            int s2 = __shfl_sync(0xffffffffu, idx, j + 2);
            int s3 = __shfl_sync(0xffffffffu, idx, j + 3);
            float d0 = __shfl_sync(0xffffffffu, dv, j);
            float d1 = __shfl_sync(0xffffffffu, dv, j + 1);
            float d2 = __shfl_sync(0xffffffffu, dv, j + 2);
            float d3 = __shfl_sync(0xffffffffu, dv, j + 3);
            uint2 v0 = __ldg(b16 + (size_t)s0 * 32 + lane);
            uint2 v1 = __ldg(b16 + (size_t)s1 * 32 + lane);
            uint2 v2 = __ldg(b16 + (size_t)s2 * 32 + lane);
            uint2 v3 = __ldg(b16 + (size_t)s3 * 32 + lane);
            {
                __half2* h = (__half2*)&v0;
                float2 f0 = __half22float2(h[0]), f1 = __half22float2(h[1]);
                a0.x = fmaf(f0.x, d0, a0.x); a0.y = fmaf(f0.y, d0, a0.y);
                a0.z = fmaf(f1.x, d0, a0.z); a0.w = fmaf(f1.y, d0, a0.w);
            }
            {
                __half2* h = (__half2*)&v1;
                float2 f0 = __half22float2(h[0]), f1 = __half22float2(h[1]);
                a1.x = fmaf(f0.x, d1, a1.x); a1.y = fmaf(f0.y, d1, a1.y);
                a1.z = fmaf(f1.x, d1, a1.z); a1.w = fmaf(f1.y, d1, a1.w);
            }
            {
                __half2* h = (__half2*)&v2;
                float2 f0 = __half22float2(h[0]), f1 = __half22float2(h[1]);
                a2.x = fmaf(f0.x, d2, a2.x); a2.y = fmaf(f0.y, d2, a2.y);
                a2.z = fmaf(f1.x, d2, a2.z); a2.w = fmaf(f1.y, d2, a2.w);
            }
            {
                __half2* h = (__half2*)&v3;
                float2 f0 = __half22float2(h[0]), f1 = __half22float2(h[1]);
                a3.x = fmaf(f0.x, d3, a3.x); a3.y = fmaf(f0.y, d3, a3.y);
                a3.z = fmaf(f1.x, d3, a3.z); a3.w = fmaf(f1.y, d3, a3.w);
            }
        }
        for (; j < cnt; j++) {
            int s0 = __shfl_sync(0xffffffffu, idx, j);
            float d0 = __shfl_sync(0xffffffffu, dv, j);
            uint2 v0 = __ldg(b16 + (size_t)s0 * 32 + lane);
            __half2* h = (__half2*)&v0;
            float2 f0 = __half22float2(h[0]), f1 = __half22float2(h[1]);
            a1.x = fmaf(f0.x, d0, a1.x); a1.y = fmaf(f0.y, d0, a1.y);
            a1.z = fmaf(f1.x, d0, a1.z); a1.w = fmaf(f1.y, d0, a1.w);
        }
    }
    float4 acc;
    acc.x = (a0.x + a1.x) + (a2.x + a3.x);
    acc.y = (a0.y + a1.y) + (a2.y + a3.y);
    acc.z = (a0.z + a1.z) + (a2.z + a3.z);
    acc.w = (a0.w + a1.w) + (a2.w + a3.w);
    float4 bv = __ldg((const float4*)bias + lane);
    float4 r;
    r.x = fmaxf(fmaf(dnode, acc.x, bv.x), 0.0f);
    r.y = fmaxf(fmaf(dnode, acc.y, bv.y), 0.0f);
    r.z = fmaxf(fmaf(dnode, acc.z, bv.z), 0.0f);
    r.w = fmaxf(fmaf(dnode, acc.w, bv.w), 0.0f);
    ((float4*)out)[(size_t)node * 32 + lane] = r;
}

// ---------------- layer-2 aggregation + fused mean-pool (sums) -------------
// fp16 gather table pre-scaled by dinv; lane handles 2 cols.
__global__ __launch_bounds__(256)
void agg2_pool_kernel(const __half* __restrict__ xws, const float* __restrict__ bias,
                      int M) {
    __shared__ float spool[64 * 64];
    __shared__ int s_gmin, s_gmax;
    int tid = threadIdx.x;
    for (int j = tid; j < 64 * 64; j += 256) spool[j] = 0.0f;
    if (tid == 0) { s_gmin = 1 << 30; s_gmax = -1; }
    __syncthreads();

    int node = blockIdx.x * 8 + (tid >> 5);
    int lane = tid & 31;
    if (node < M) {
        const unsigned* b16 = (const unsigned*)xws;   // 2 halfs per uint; 32/row
        unsigned sv = __ldg(b16 + (size_t)node * 32 + lane);
        float2 a0 = __half22float2(*(__half2*)&sv);   // self loop
        float2 a1 = make_float2(0.f, 0.f);
        float2 a2 = make_float2(0.f, 0.f);
        float2 a3 = make_float2(0.f, 0.f);
        int s = g_rowptr[node], e = g_rowptr[node + 1];
        for (int cs = s; cs < e; cs += 32) {
            int cnt = e - cs; if (cnt > 32) cnt = 32;
            int idx = (cs + lane < e) ? g_colidx[cs + lane] : 0;
            int j = 0;
            for (; j + 4 <= cnt; j += 4) {
                int s0 = __shfl_sync(0xffffffffu, idx, j);
                int s1 = __shfl_sync(0xffffffffu, idx, j + 1);
                int s2 = __shfl_sync(0xffffffffu, idx, j + 2);
                int s3 = __shfl_sync(0xffffffffu, idx, j + 3);
                unsigned v0 = __ldg(b16 + (size_t)s0 * 32 + lane);
                unsigned v1 = __ldg(b16 + (size_t)s1 * 32 + lane);
                unsigned v2 = __ldg(b16 + (size_t)s2 * 32 + lane);
                unsigned v3 = __ldg(b16 + (size_t)s3 * 32 + lane);
                float2 f0 = __half22float2(*(__half2*)&v0);
                float2 f1 = __half22float2(*(__half2*)&v1);
                float2 f2 = __half22float2(*(__half2*)&v2);
                float2 f3 = __half22float2(*(__half2*)&v3);
                a0.x += f0.x; a0.y += f0.y;
                a1.x += f1.x; a1.y += f1.y;
                a2.x += f2.x; a2.y += f2.y;
                a3.x += f3.x; a3.y += f3.y;
            }
            for (; j < cnt; j++) {
                int s0 = __shfl_sync(0xffffffffu, idx, j);
                unsigned v0 = __ldg(b16 + (size_t)s0 * 32 + lane);
                float2 f0 = __half22float2(*(__half2*)&v0);
                a1.x += f0.x; a1.y += f0.y;
            }
        }
        float accx = (a0.x + a1.x) + (a2.x + a3.x);
        float accy = (a0.y + a1.y) + (a2.y + a3.y);
        float di = g_dinv[node];
        float2 bv = __ldg((const float2*)bias + lane);
        float rx = fmaf(di, accx, bv.x);
        float ry = fmaf(di, accy, bv.y);
        int g = g_batch[node];
        if (lane == 0) { atomicMin(&s_gmin, g); atomicMax(&s_gmax, g); }
        atomicAdd(&spool[g * 64 + lane * 2], rx);
        atomicAdd(&spool[g * 64 + lane * 2 + 1], ry);
    }
    __syncthreads();
    int gmin = s_gmin, gmax = s_gmax;
    if (gmax >= gmin) {
        int lo = gmin * 64;
        int cnt = (gmax - gmin + 1) * 64;
        for (int j = tid; j < cnt; j += 256)
            atomicAdd(&g_gsum[lo + j], spool[lo + j]);
    }
}

__global__ void k_final(float* __restrict__ out, int n) {
    int i = blockIdx.x * blockDim.x + threadIdx.x;
    if (i < n) out[i] = g_gsum[i] / fmaxf(g_gcnt[i >> 6], 1.0f);
}

// ---------------- launch ----------------------------------------------------
extern "C" void kernel_launch(void* const* d_in, const int* in_sizes, int n_in,
                              void* d_out, int out_size) {
    const float* x  = (const float*)d_in[0];
    const void*  ei = d_in[1];
    const void*  bp = d_in[2];
    const float* W1 = (const float*)d_in[3];
    const float* b1 = (const float*)d_in[4];
    const float* W2 = (const float*)d_in[5];
    const float* b2 = (const float*)d_in[6];
    float* out = (float*)d_out;

    int N    = in_sizes[2];          // 50000
    int E    = in_sizes[1] / 2;      // 800000
    int din  = in_sizes[0] / N;      // 128
    int dhid = in_sizes[4];          // 128
    int NG   = out_size / in_sizes[6];

    __half *p_xws1, *p_xws2;
    float *p_h;
    cudaGetSymbolAddress((void**)&p_xws1, g_xws1h);
    cudaGetSymbolAddress((void**)&p_h,    g_h);
    cudaGetSymbolAddress((void**)&p_xws2, g_xws2h);

    // One-time side-stream + events for fork/join graph branches.
    static cudaStream_t s2 = nullptr;
    static cudaEvent_t ev_fork = nullptr, ev_join = nullptr;
    if (s2 == nullptr) {
        cudaStreamCreateWithFlags(&s2, cudaStreamNonBlocking);
        cudaEventCreateWithFlags(&ev_fork, cudaEventDisableTiming);
        cudaEventCreateWithFlags(&ev_join, cudaEventDisableTiming);
    }

    int nbE = (E + 255) / 256;
    int nbI = ((N > 4096 ? N : 4096) + 255) / 256;
    int nbS = (N + SCAN_CHUNK - 1) / SCAN_CHUNK;

    // ---- init (both branches depend on it) ----
    k_init_detect<<<nbI, 256>>>(N, ei);

    // ---- fork: branch B = gemm1 (independent of graph structure) ----
    cudaEventRecord(ev_fork, 0);
    cudaStreamWaitEvent(s2, ev_fork, 0);
    gemm_kernel<128, 256, false><<<(N + 127) / 128, 256, 0, s2>>>(x, W1, p_xws1, N, din);
    cudaEventRecord(ev_join, s2);

    // ---- branch A: CSR build on main stream ----
    k_conv_fused<<<nbE, 256>>>(ei, bp, E, N, NG > 64 ? 64 : NG);
    k_scanA<<<nbS, SCAN_CHUNK>>>(N);
    k_scanB<<<1, 128>>>(nbS);
    k_scanC<<<nbS, SCAN_CHUNK>>>(N);
    k_fill<<<nbE, 256>>>(E);

    // ---- join ----
    cudaStreamWaitEvent(0, ev_join, 0);

    // layer 1 aggregation (applies dinv[src] and dinv[dst])
    agg1_kernel<<<(N + 7) / 8, 256>>>(p_xws1, b1, p_h, N);

    // layer 2 + fused pooling
    gemm_kernel<64, 128, true><<<(N + 127) / 128, 128>>>(p_h, W2, p_xws2, N, dhid);
    agg2_pool_kernel<<<(N + 7) / 8, 256>>>(p_xws2, b2, N);

    k_final<<<(out_size + 255) / 256, 256>>>(out, out_size);
}